// round 1
// baseline (speedup 1.0000x reference)
#include <cuda_runtime.h>
#include <cstdint>

// Problem constants (fixed shapes from reference)
#define NN   50000      // nodes
#define NE   800000     // edges
#define FIN  128
#define FHID 384
#define FOUT 256

// ----------------------------- scratch (device globals; no allocs allowed) ---
__device__ float g_agg1[NN * FIN];            // 25.6 MB
__device__ float g_x1[(size_t)NN * FHID];     // 76.8 MB
__device__ float g_y[(size_t)NN * FOUT];      // 51.2 MB
__device__ int   g_deg_out[NN];
__device__ int   g_deg_in[NN];
__device__ float g_out_norm[NN];
__device__ float g_in_norm[NN];

// ----------------------------- helpers --------------------------------------
__device__ __forceinline__ void red_add_v4(float* p, float4 v) {
    // vectorized no-return global reduction (sm_90+): 1 instr for 16B
    asm volatile("red.global.add.v4.f32 [%0], {%1, %2, %3, %4};"
                 :: "l"(p), "f"(v.x), "f"(v.y), "f"(v.z), "f"(v.w)
                 : "memory");
}

// ----------------------------- small kernels --------------------------------
__global__ void zero_f4_kernel(float4* __restrict__ p, int n4) {
    int i = blockIdx.x * blockDim.x + threadIdx.x;
    if (i < n4) p[i] = make_float4(0.f, 0.f, 0.f, 0.f);
}

__global__ void degree_kernel(const int* __restrict__ ei,
                              int* __restrict__ dout, int* __restrict__ din) {
    int e = blockIdx.x * blockDim.x + threadIdx.x;
    if (e < NE) {
        atomicAdd(&dout[ei[e]], 1);
        atomicAdd(&din[ei[NE + e]], 1);
    }
}

__global__ void norm_kernel(const int* __restrict__ dout, const int* __restrict__ din,
                            float* __restrict__ onorm, float* __restrict__ inorm) {
    int n = blockIdx.x * blockDim.x + threadIdx.x;
    if (n < NN) {
        onorm[n] = rsqrtf((float)max(dout[n], 1));
        inorm[n] = rsqrtf((float)max(din[n], 1));
    }
}

// agg1: one warp per edge; 32 lanes x float4 = 128 floats.
// agg1[dst] += features[src] * out_norm[src]
__global__ void agg1_kernel(const int* __restrict__ ei,
                            const float* __restrict__ feat,
                            const float* __restrict__ onorm,
                            float* __restrict__ agg) {
    int gw = (blockIdx.x * blockDim.x + threadIdx.x) >> 5;
    if (gw >= NE) return;
    int lane = threadIdx.x & 31;
    int src = __ldg(&ei[gw]);
    int dst = __ldg(&ei[NE + gw]);
    float s = __ldg(&onorm[src]);
    float4 v = *(const float4*)(feat + (size_t)src * FIN + lane * 4);
    v.x *= s; v.y *= s; v.z *= s; v.w *= s;
    red_add_v4(agg + (size_t)dst * FIN + lane * 4, v);
}

// agg2: one warp per edge; 2 x (32 lanes x float4) = 256 floats.
// out[dst] += y[src]   (y already pre-scaled by out_norm in GEMM2 epilogue)
__global__ void agg2_kernel(const int* __restrict__ ei,
                            const float* __restrict__ y,
                            float* __restrict__ out) {
    int gw = (blockIdx.x * blockDim.x + threadIdx.x) >> 5;
    if (gw >= NE) return;
    int lane = threadIdx.x & 31;
    int src = __ldg(&ei[gw]);
    int dst = __ldg(&ei[NE + gw]);
    const float* yr = y + (size_t)src * FOUT;
    float* orow = out + (size_t)dst * FOUT;
#pragma unroll
    for (int k = 0; k < 2; k++) {
        float4 v = *(const float4*)(yr + k * 128 + lane * 4);
        red_add_v4(orow + k * 128 + lane * 4, v);
    }
}

// out[n][c] = out[n][c] * in_norm[n] + b2[c]
__global__ void finalize_kernel(float* __restrict__ out,
                                const float* __restrict__ inorm,
                                const float* __restrict__ b2) {
    int i = blockIdx.x * blockDim.x + threadIdx.x;
    const int n4 = NN * (FOUT / 4);
    if (i >= n4) return;
    int n  = i / (FOUT / 4);
    int c4 = i % (FOUT / 4);
    float s = inorm[n];
    float4 v = ((float4*)out)[i];
    float4 b = ((const float4*)b2)[c4];
    v.x = v.x * s + b.x;
    v.y = v.y * s + b.y;
    v.z = v.z * s + b.z;
    v.w = v.w * s + b.w;
    ((float4*)out)[i] = v;
}

// ----------------------------- GEMM -----------------------------------------
// C[M,N] = epi( (A[M,K] @ B[K,N]) * rowscale[row] (+ bias[col]) (relu) )
// Tile: BM=128, BN=64, BK=16; 256 threads; 8x4 micro-tile per thread.
// Requires: K % 16 == 0, N % 64 == 0 (true: K in {128,384}, N in {384,256}).
template<bool RELU, bool HAS_BIAS>
__global__ __launch_bounds__(256)
void gemm_rs_kernel(const float* __restrict__ A, const float* __restrict__ B,
                    float* __restrict__ C,
                    const float* __restrict__ rowscale,
                    const float* __restrict__ bias,
                    int M, int N, int K) {
    constexpr int BM = 128, BN = 64, BK = 16, TM = 8, TN = 4;
    __shared__ float As[BK][BM + 4];   // +4 pad keeps 16B alignment, spreads banks
    __shared__ float Bs[BK][BN];

    const int tid   = threadIdx.x;
    const int brow0 = blockIdx.y * BM;
    const int bcol0 = blockIdx.x * BN;
    const int tc = tid & 15;   // 0..15 (col group of TN=4)
    const int tr = tid >> 4;   // 0..15 (row group of TM=8)

    float acc[TM][TN];
#pragma unroll
    for (int i = 0; i < TM; i++)
#pragma unroll
        for (int j = 0; j < TN; j++) acc[i][j] = 0.f;

    for (int k0 = 0; k0 < K; k0 += BK) {
        // Load A tile (BM x BK), transposed into As[k][m]. 512 float4, 2/thread.
#pragma unroll
        for (int l = 0; l < 2; l++) {
            int idx = tid + l * 256;
            int ar  = idx >> 2;        // 0..127
            int ac4 = idx & 3;         // 0..3 -> k offset ac4*4
            int grow = brow0 + ar;
            float4 v = make_float4(0.f, 0.f, 0.f, 0.f);
            if (grow < M)
                v = *(const float4*)(A + (size_t)grow * K + k0 + ac4 * 4);
            As[ac4 * 4 + 0][ar] = v.x;
            As[ac4 * 4 + 1][ar] = v.y;
            As[ac4 * 4 + 2][ar] = v.z;
            As[ac4 * 4 + 3][ar] = v.w;
        }
        // Load B tile (BK x BN). 256 float4, 1/thread.
        {
            int brw = tid >> 4;        // 0..15
            int bc4 = tid & 15;        // 0..15
            float4 v = *(const float4*)(B + (size_t)(k0 + brw) * N + bcol0 + bc4 * 4);
            *(float4*)&Bs[brw][bc4 * 4] = v;
        }
        __syncthreads();

#pragma unroll
        for (int kk = 0; kk < BK; kk++) {
            float4 a0 = *(float4*)&As[kk][tr * TM];
            float4 a1 = *(float4*)&As[kk][tr * TM + 4];
            float4 b0 = *(float4*)&Bs[kk][tc * TN];
            float a[TM] = {a0.x, a0.y, a0.z, a0.w, a1.x, a1.y, a1.z, a1.w};
            float b[TN] = {b0.x, b0.y, b0.z, b0.w};
#pragma unroll
            for (int i = 0; i < TM; i++)
#pragma unroll
                for (int j = 0; j < TN; j++)
                    acc[i][j] = fmaf(a[i], b[j], acc[i][j]);
        }
        __syncthreads();
    }

    // Epilogue: scale by rowscale, optional bias, optional relu, float4 store.
    const int col = bcol0 + tc * TN;
    float4 bb = make_float4(0.f, 0.f, 0.f, 0.f);
    if (HAS_BIAS) bb = *(const float4*)(bias + col);
#pragma unroll
    for (int i = 0; i < TM; i++) {
        int row = brow0 + tr * TM + i;
        if (row < M) {
            float rs = rowscale[row];
            float4 o;
            o.x = acc[i][0] * rs + bb.x;
            o.y = acc[i][1] * rs + bb.y;
            o.z = acc[i][2] * rs + bb.z;
            o.w = acc[i][3] * rs + bb.w;
            if (RELU) {
                o.x = fmaxf(o.x, 0.f); o.y = fmaxf(o.y, 0.f);
                o.z = fmaxf(o.z, 0.f); o.w = fmaxf(o.w, 0.f);
            }
            *(float4*)(C + (size_t)row * N + col) = o;
        }
    }
}

// ----------------------------- launch ---------------------------------------
extern "C" void kernel_launch(void* const* d_in, const int* in_sizes, int n_in,
                              void* d_out, int out_size) {
    // Map inputs by element count (order-robust).
    const float *features = nullptr, *W1 = nullptr, *b1 = nullptr,
                *W2 = nullptr, *b2 = nullptr;
    const int* ei = nullptr;
    for (int i = 0; i < n_in; i++) {
        switch (in_sizes[i]) {
            case NN * FIN:      features = (const float*)d_in[i]; break;
            case FIN * FHID:    W1 = (const float*)d_in[i]; break;
            case FHID:          b1 = (const float*)d_in[i]; break;
            case FHID * FOUT:   W2 = (const float*)d_in[i]; break;
            case FOUT:          b2 = (const float*)d_in[i]; break;
            case 2 * NE:        ei = (const int*)d_in[i]; break;
            default: break;
        }
    }
    float* out = (float*)d_out;

    float *agg1, *x1, *y, *onorm, *inorm;
    int *dout, *din;
    cudaGetSymbolAddress((void**)&agg1,  g_agg1);
    cudaGetSymbolAddress((void**)&x1,    g_x1);
    cudaGetSymbolAddress((void**)&y,     g_y);
    cudaGetSymbolAddress((void**)&onorm, g_out_norm);
    cudaGetSymbolAddress((void**)&inorm, g_in_norm);
    cudaGetSymbolAddress((void**)&dout,  g_deg_out);
    cudaGetSymbolAddress((void**)&din,   g_deg_in);

    const int T = 256;

    // Zero accumulation buffers (agg1, out) and degree counters.
    {
        int n4 = NN * FIN / 4;
        zero_f4_kernel<<<(n4 + T - 1) / T, T>>>((float4*)agg1, n4);
        n4 = NN * FOUT / 4;
        zero_f4_kernel<<<(n4 + T - 1) / T, T>>>((float4*)out, n4);
        n4 = NN / 4;  // 50000 ints = 12500 float4
        zero_f4_kernel<<<(n4 + T - 1) / T, T>>>((float4*)dout, n4);
        zero_f4_kernel<<<(n4 + T - 1) / T, T>>>((float4*)din, n4);
    }

    // Degrees + norms
    degree_kernel<<<(NE + T - 1) / T, T>>>(ei, dout, din);
    norm_kernel<<<(NN + T - 1) / T, T>>>(dout, din, onorm, inorm);

    // agg1[dst] += features[src] * out_norm[src]   (warp per edge)
    {
        long long threads = (long long)NE * 32;
        agg1_kernel<<<(unsigned)((threads + T - 1) / T), T>>>(ei, features, onorm, agg1);
    }

    // x1 = relu( (agg1 * in_norm[row]) @ W1 + b1 )   [NN, 384]
    {
        dim3 grid(FHID / 64, (NN + 127) / 128);
        gemm_rs_kernel<true, true><<<grid, 256>>>(agg1, W1, x1, inorm, b1,
                                                  NN, FHID, FIN);
    }

    // y = out_norm[row] * (x1 @ W2)   [NN, 256]
    {
        dim3 grid(FOUT / 64, (NN + 127) / 128);
        gemm_rs_kernel<false, false><<<grid, 256>>>(x1, W2, y, onorm, nullptr,
                                                    NN, FOUT, FHID);
    }

    // out[dst] += y[src]   (warp per edge)
    {
        long long threads = (long long)NE * 32;
        agg2_kernel<<<(unsigned)((threads + T - 1) / T), T>>>(ei, y, out);
    }

    // out = out * in_norm[row] + b2[col]
    {
        int n4 = NN * FOUT / 4;
        finalize_kernel<<<(n4 + T - 1) / T, T>>>(out, inorm, b2);
    }
}

// round 2
// speedup vs baseline: 1.3781x; 1.3781x over previous
#include <cuda_runtime.h>
#include <cstdint>

// Problem constants (fixed shapes from reference)
#define NN   50000      // nodes
#define NE   800000     // edges
#define FIN  128
#define FHID 384
#define FOUT 256

// ----------------------------- scratch (device globals; no allocs allowed) ---
__device__ float g_agg1[NN * FIN];            // 25.6 MB
__device__ float g_x1[(size_t)NN * FHID];     // 76.8 MB
__device__ float g_y[(size_t)NN * FOUT];      // 51.2 MB
__device__ int   g_deg_out[NN];
__device__ int   g_deg_in[NN];
__device__ float g_out_norm[NN];
__device__ float g_in_norm[NN];

// ----------------------------- helpers --------------------------------------
__device__ __forceinline__ void red_add_v4(float* p, float4 v) {
    asm volatile("red.global.add.v4.f32 [%0], {%1, %2, %3, %4};"
                 :: "l"(p), "f"(v.x), "f"(v.y), "f"(v.z), "f"(v.w)
                 : "memory");
}

__device__ __forceinline__ unsigned f2tf32(float x) {
    unsigned r;
    asm("cvt.rna.tf32.f32 %0, %1;" : "=r"(r) : "f"(x));
    return r;
}

__device__ __forceinline__ void mma_tf32(float& c0, float& c1, float& c2, float& c3,
                                         unsigned a0, unsigned a1, unsigned a2, unsigned a3,
                                         unsigned b0, unsigned b1) {
    asm volatile("mma.sync.aligned.m16n8k8.row.col.f32.tf32.tf32.f32 "
                 "{%0,%1,%2,%3}, {%4,%5,%6,%7}, {%8,%9}, {%0,%1,%2,%3};"
                 : "+f"(c0), "+f"(c1), "+f"(c2), "+f"(c3)
                 : "r"(a0), "r"(a1), "r"(a2), "r"(a3), "r"(b0), "r"(b1));
}

// ----------------------------- small kernels --------------------------------
__global__ void zero_f4_kernel(float4* __restrict__ p, int n4) {
    int i = blockIdx.x * blockDim.x + threadIdx.x;
    if (i < n4) p[i] = make_float4(0.f, 0.f, 0.f, 0.f);
}

__global__ void degree_kernel(const int* __restrict__ ei,
                              int* __restrict__ dout, int* __restrict__ din) {
    int e = blockIdx.x * blockDim.x + threadIdx.x;
    if (e < NE) {
        atomicAdd(&dout[ei[e]], 1);
        atomicAdd(&din[ei[NE + e]], 1);
    }
}

__global__ void norm_kernel(const int* __restrict__ dout, const int* __restrict__ din,
                            float* __restrict__ onorm, float* __restrict__ inorm) {
    int n = blockIdx.x * blockDim.x + threadIdx.x;
    if (n < NN) {
        onorm[n] = rsqrtf((float)max(dout[n], 1));
        inorm[n] = rsqrtf((float)max(din[n], 1));
    }
}

// agg1[dst] += features[src] * out_norm[src]   (warp per edge, float4 lanes)
__global__ void agg1_kernel(const int* __restrict__ ei,
                            const float* __restrict__ feat,
                            const float* __restrict__ onorm,
                            float* __restrict__ agg) {
    int gw = (blockIdx.x * blockDim.x + threadIdx.x) >> 5;
    if (gw >= NE) return;
    int lane = threadIdx.x & 31;
    int src = __ldg(&ei[gw]);
    int dst = __ldg(&ei[NE + gw]);
    float s = __ldg(&onorm[src]);
    float4 v = *(const float4*)(feat + (size_t)src * FIN + lane * 4);
    v.x *= s; v.y *= s; v.z *= s; v.w *= s;
    red_add_v4(agg + (size_t)dst * FIN + lane * 4, v);
}

// out[dst] += y[src]   (warp per edge; y pre-scaled by out_norm)
__global__ void agg2_kernel(const int* __restrict__ ei,
                            const float* __restrict__ y,
                            float* __restrict__ out) {
    int gw = (blockIdx.x * blockDim.x + threadIdx.x) >> 5;
    if (gw >= NE) return;
    int lane = threadIdx.x & 31;
    int src = __ldg(&ei[gw]);
    int dst = __ldg(&ei[NE + gw]);
    const float* yr = y + (size_t)src * FOUT;
    float* orow = out + (size_t)dst * FOUT;
#pragma unroll
    for (int k = 0; k < 2; k++) {
        float4 v = *(const float4*)(yr + k * 128 + lane * 4);
        red_add_v4(orow + k * 128 + lane * 4, v);
    }
}

// out[n][c] = out[n][c] * in_norm[n] + b2[c]
__global__ void finalize_kernel(float* __restrict__ out,
                                const float* __restrict__ inorm,
                                const float* __restrict__ b2) {
    int i = blockIdx.x * blockDim.x + threadIdx.x;
    const int n4 = NN * (FOUT / 4);
    if (i >= n4) return;
    int n  = i / (FOUT / 4);
    int c4 = i % (FOUT / 4);
    float s = inorm[n];
    float4 v = ((float4*)out)[i];
    float4 b = ((const float4*)b2)[c4];
    v.x = v.x * s + b.x;
    v.y = v.y * s + b.y;
    v.z = v.z * s + b.z;
    v.w = v.w * s + b.w;
    ((float4*)out)[i] = v;
}

// ----------------------------- tf32 tensor GEMM ------------------------------
// C[M,N] = epi( (A[M,K] @ B[K,N]) * rowscale[row] (+ bias[col]) (relu) )
// BM=128, BN=64, BK=32; 256 threads = 8 warps (4 M x 2 N), warp tile 32x32.
// mma.sync m16n8k8 tf32. Requires K%32==0, N%64==0 (K in {128,384}, N in {384,256}).
template<bool RELU, bool HAS_BIAS>
__global__ __launch_bounds__(256)
void gemm_tf32_kernel(const float* __restrict__ A, const float* __restrict__ B,
                      float* __restrict__ C,
                      const float* __restrict__ rowscale,
                      const float* __restrict__ bias,
                      int M, int N, int K) {
    constexpr int BM = 128, BN = 64, BK = 32;
    __shared__ unsigned As[BM][BK + 4];   // stride 36: conflict-free frag loads
    __shared__ unsigned Bs[BK][BN + 4];   // stride 68: <=2-way on frag loads

    const int tid  = threadIdx.x;
    const int warp = tid >> 5;
    const int lane = tid & 31;
    const int wm = warp & 3;              // 0..3  -> 32-row slice
    const int wn = warp >> 2;             // 0..1  -> 32-col slice
    const int gid  = lane >> 2;           // groupID 0..7
    const int tig  = lane & 3;            // thread-in-group 0..3

    const int brow0 = blockIdx.y * BM;
    const int bcol0 = blockIdx.x * BN;

    float acc[2][4][4];
#pragma unroll
    for (int mt = 0; mt < 2; mt++)
#pragma unroll
        for (int nt = 0; nt < 4; nt++)
#pragma unroll
            for (int f = 0; f < 4; f++) acc[mt][nt][f] = 0.f;

    for (int k0 = 0; k0 < K; k0 += BK) {
        // ---- A tile: 128x32 floats = 1024 float4; 4 per thread. As[m][k].
#pragma unroll
        for (int l = 0; l < 4; l++) {
            int idx = tid + l * 256;
            int r   = idx >> 3;            // 0..127
            int c4  = idx & 7;             // 0..7
            int grow = brow0 + r;
            float4 v = make_float4(0.f, 0.f, 0.f, 0.f);
            if (grow < M)
                v = *(const float4*)(A + (size_t)grow * K + k0 + c4 * 4);
            uint4 t;
            t.x = f2tf32(v.x); t.y = f2tf32(v.y);
            t.z = f2tf32(v.z); t.w = f2tf32(v.w);
            *(uint4*)&As[r][c4 * 4] = t;
        }
        // ---- B tile: 32x64 floats = 512 float4; 2 per thread. Bs[k][n].
#pragma unroll
        for (int l = 0; l < 2; l++) {
            int idx = tid + l * 256;
            int kr  = idx >> 4;            // 0..31
            int nc4 = idx & 15;            // 0..15
            float4 v = *(const float4*)(B + (size_t)(k0 + kr) * N + bcol0 + nc4 * 4);
            uint4 t;
            t.x = f2tf32(v.x); t.y = f2tf32(v.y);
            t.z = f2tf32(v.z); t.w = f2tf32(v.w);
            *(uint4*)&Bs[kr][nc4 * 4] = t;
        }
        __syncthreads();

#pragma unroll
        for (int ks = 0; ks < BK; ks += 8) {
            unsigned a[2][4];
#pragma unroll
            for (int mt = 0; mt < 2; mt++) {
                int r = wm * 32 + mt * 16 + gid;
                a[mt][0] = As[r][ks + tig];
                a[mt][1] = As[r + 8][ks + tig];
                a[mt][2] = As[r][ks + 4 + tig];
                a[mt][3] = As[r + 8][ks + 4 + tig];
            }
            unsigned b[4][2];
#pragma unroll
            for (int nt = 0; nt < 4; nt++) {
                int n = wn * 32 + nt * 8 + gid;
                b[nt][0] = Bs[ks + tig][n];
                b[nt][1] = Bs[ks + 4 + tig][n];
            }
#pragma unroll
            for (int mt = 0; mt < 2; mt++)
#pragma unroll
                for (int nt = 0; nt < 4; nt++)
                    mma_tf32(acc[mt][nt][0], acc[mt][nt][1],
                             acc[mt][nt][2], acc[mt][nt][3],
                             a[mt][0], a[mt][1], a[mt][2], a[mt][3],
                             b[nt][0], b[nt][1]);
        }
        __syncthreads();
    }

    // ---- Epilogue: rowscale, optional bias, optional relu, float2 stores.
#pragma unroll
    for (int mt = 0; mt < 2; mt++) {
        int r0 = brow0 + wm * 32 + mt * 16 + gid;     // first row of frag
        int r1 = r0 + 8;
        float rs0 = (r0 < M) ? __ldg(&rowscale[r0]) : 0.f;
        float rs1 = (r1 < M) ? __ldg(&rowscale[r1]) : 0.f;
#pragma unroll
        for (int nt = 0; nt < 4; nt++) {
            int c = bcol0 + wn * 32 + nt * 8 + 2 * tig;
            float2 bb = make_float2(0.f, 0.f);
            if (HAS_BIAS) bb = *(const float2*)(bias + c);
            float2 o0, o1;
            o0.x = acc[mt][nt][0] * rs0 + bb.x;
            o0.y = acc[mt][nt][1] * rs0 + bb.y;
            o1.x = acc[mt][nt][2] * rs1 + bb.x;
            o1.y = acc[mt][nt][3] * rs1 + bb.y;
            if (RELU) {
                o0.x = fmaxf(o0.x, 0.f); o0.y = fmaxf(o0.y, 0.f);
                o1.x = fmaxf(o1.x, 0.f); o1.y = fmaxf(o1.y, 0.f);
            }
            if (r0 < M) *(float2*)(C + (size_t)r0 * N + c) = o0;
            if (r1 < M) *(float2*)(C + (size_t)r1 * N + c) = o1;
        }
    }
}

// ----------------------------- launch ---------------------------------------
extern "C" void kernel_launch(void* const* d_in, const int* in_sizes, int n_in,
                              void* d_out, int out_size) {
    const float *features = nullptr, *W1 = nullptr, *b1 = nullptr,
                *W2 = nullptr, *b2 = nullptr;
    const int* ei = nullptr;
    for (int i = 0; i < n_in; i++) {
        switch (in_sizes[i]) {
            case NN * FIN:      features = (const float*)d_in[i]; break;
            case FIN * FHID:    W1 = (const float*)d_in[i]; break;
            case FHID:          b1 = (const float*)d_in[i]; break;
            case FHID * FOUT:   W2 = (const float*)d_in[i]; break;
            case FOUT:          b2 = (const float*)d_in[i]; break;
            case 2 * NE:        ei = (const int*)d_in[i]; break;
            default: break;
        }
    }
    float* out = (float*)d_out;

    float *agg1, *x1, *y, *onorm, *inorm;
    int *dout, *din;
    cudaGetSymbolAddress((void**)&agg1,  g_agg1);
    cudaGetSymbolAddress((void**)&x1,    g_x1);
    cudaGetSymbolAddress((void**)&y,     g_y);
    cudaGetSymbolAddress((void**)&onorm, g_out_norm);
    cudaGetSymbolAddress((void**)&inorm, g_in_norm);
    cudaGetSymbolAddress((void**)&dout,  g_deg_out);
    cudaGetSymbolAddress((void**)&din,   g_deg_in);

    const int T = 256;

    {
        int n4 = NN * FIN / 4;
        zero_f4_kernel<<<(n4 + T - 1) / T, T>>>((float4*)agg1, n4);
        n4 = NN * FOUT / 4;
        zero_f4_kernel<<<(n4 + T - 1) / T, T>>>((float4*)out, n4);
        n4 = NN / 4;
        zero_f4_kernel<<<(n4 + T - 1) / T, T>>>((float4*)dout, n4);
        zero_f4_kernel<<<(n4 + T - 1) / T, T>>>((float4*)din, n4);
    }

    degree_kernel<<<(NE + T - 1) / T, T>>>(ei, dout, din);
    norm_kernel<<<(NN + T - 1) / T, T>>>(dout, din, onorm, inorm);

    // agg1[dst] += features[src] * out_norm[src]
    {
        long long threads = (long long)NE * 32;
        agg1_kernel<<<(unsigned)((threads + T - 1) / T), T>>>(ei, features, onorm, agg1);
    }

    // x1 = relu( inorm[row] * (agg1 @ W1) + b1 )   [NN, 384]
    {
        dim3 grid(FHID / 64, (NN + 127) / 128);
        gemm_tf32_kernel<true, true><<<grid, 256>>>(agg1, W1, x1, inorm, b1,
                                                    NN, FHID, FIN);
    }

    // y = onorm[row] * (x1 @ W2)   [NN, 256]
    {
        dim3 grid(FOUT / 64, (NN + 127) / 128);
        gemm_tf32_kernel<false, false><<<grid, 256>>>(x1, W2, y, onorm, nullptr,
                                                      NN, FOUT, FHID);
    }

    // out[dst] += y[src]
    {
        long long threads = (long long)NE * 32;
        agg2_kernel<<<(unsigned)((threads + T - 1) / T), T>>>(ei, y, out);
    }

    // out = out * in_norm[row] + b2[col]
    {
        int n4 = NN * FOUT / 4;
        finalize_kernel<<<(n4 + T - 1) / T, T>>>(out, inorm, b2);
    }
}

// round 3
// speedup vs baseline: 1.6703x; 1.2121x over previous
#include <cuda_runtime.h>
#include <cstdint>

// Problem constants (fixed shapes from reference)
#define NN   50000      // nodes
#define NE   800000     // edges
#define FIN  128
#define FHID 384
#define FOUT 256

// ----------------------------- scratch (device globals; no allocs allowed) ---
__device__ float g_agg1[NN * FIN];            // 25.6 MB
__device__ float g_x1[(size_t)NN * FHID];     // 76.8 MB
__device__ float g_y[(size_t)NN * FOUT];      // 51.2 MB
__device__ int   g_deg_out[NN];
__device__ int   g_deg_in[NN];
__device__ float g_out_norm[NN];
__device__ float g_in_norm[NN];
__device__ int   g_off[NN + 1];
__device__ int   g_cursor[NN];
__device__ int   g_csr_src[NE];

// ----------------------------- helpers --------------------------------------
__device__ __forceinline__ unsigned f2tf32(float x) {
    unsigned r;
    asm("cvt.rna.tf32.f32 %0, %1;" : "=r"(r) : "f"(x));
    return r;
}

__device__ __forceinline__ void mma_tf32(float& c0, float& c1, float& c2, float& c3,
                                         unsigned a0, unsigned a1, unsigned a2, unsigned a3,
                                         unsigned b0, unsigned b1) {
    asm volatile("mma.sync.aligned.m16n8k8.row.col.f32.tf32.tf32.f32 "
                 "{%0,%1,%2,%3}, {%4,%5,%6,%7}, {%8,%9}, {%0,%1,%2,%3};"
                 : "+f"(c0), "+f"(c1), "+f"(c2), "+f"(c3)
                 : "r"(a0), "r"(a1), "r"(a2), "r"(a3), "r"(b0), "r"(b1));
}

// ----------------------------- small kernels --------------------------------
__global__ void zero_int_kernel(int* __restrict__ p, int n) {
    int i = blockIdx.x * blockDim.x + threadIdx.x;
    if (i < n) p[i] = 0;
}

__global__ void degree_kernel(const int* __restrict__ ei,
                              int* __restrict__ dout, int* __restrict__ din) {
    int e = blockIdx.x * blockDim.x + threadIdx.x;
    if (e < NE) {
        atomicAdd(&dout[ei[e]], 1);
        atomicAdd(&din[ei[NE + e]], 1);
    }
}

__global__ void norm_kernel(const int* __restrict__ dout, const int* __restrict__ din,
                            float* __restrict__ onorm, float* __restrict__ inorm) {
    int n = blockIdx.x * blockDim.x + threadIdx.x;
    if (n < NN) {
        onorm[n] = rsqrtf((float)max(dout[n], 1));
        inorm[n] = rsqrtf((float)max(din[n], 1));
    }
}

// Single-block exclusive scan over deg_in -> off, cursor (50k ints).
__global__ void scan_kernel(const int* __restrict__ deg,
                            int* __restrict__ off, int* __restrict__ cursor) {
    constexpr int T = 1024;
    constexpr int CHUNK = (NN + T - 1) / T;   // 49
    __shared__ int ssum[T];
    int t = threadIdx.x;
    int base = t * CHUNK;
    int s = 0;
#pragma unroll 4
    for (int i = 0; i < CHUNK; i++) {
        int idx = base + i;
        if (idx < NN) s += deg[idx];
    }
    ssum[t] = s;
    __syncthreads();
    // Hillis-Steele inclusive scan
    for (int d = 1; d < T; d <<= 1) {
        int v = (t >= d) ? ssum[t - d] : 0;
        __syncthreads();
        if (t >= d) ssum[t] += v;
        __syncthreads();
    }
    int run = (t > 0) ? ssum[t - 1] : 0;     // exclusive prefix of this chunk
    for (int i = 0; i < CHUNK; i++) {
        int idx = base + i;
        if (idx < NN) {
            off[idx] = run;
            cursor[idx] = run;
            run += deg[idx];
        }
    }
    if (t == T - 1) off[NN] = NE;
}

// Counting-sort scatter: csr_src grouped by dst.
__global__ void scatter_kernel(const int* __restrict__ ei,
                               int* __restrict__ cursor,
                               int* __restrict__ csr_src) {
    int e = blockIdx.x * blockDim.x + threadIdx.x;
    if (e < NE) {
        int src = ei[e];
        int dst = ei[NE + e];
        int pos = atomicAdd(&cursor[dst], 1);
        csr_src[pos] = src;
    }
}

// agg1[n] = sum_{src in N(n)} feat[src] * onorm[src]   (warp per node, gather)
__global__ void agg1_gather_kernel(const int* __restrict__ off,
                                   const int* __restrict__ csr_src,
                                   const float* __restrict__ feat,
                                   const float* __restrict__ onorm,
                                   float* __restrict__ agg) {
    int n = (blockIdx.x * blockDim.x + threadIdx.x) >> 5;
    if (n >= NN) return;
    int lane = threadIdx.x & 31;
    int beg = off[n], end = off[n + 1];
    float4 acc = make_float4(0.f, 0.f, 0.f, 0.f);
    for (int j = beg; j < end; j += 32) {
        int m = min(32, end - j);
        int s  = (lane < m) ? __ldg(&csr_src[j + lane]) : 0;
        float w = (lane < m) ? __ldg(&onorm[s]) : 0.f;
        for (int k = 0; k < m; k++) {
            int   ss = __shfl_sync(0xffffffffu, s, k);
            float ww = __shfl_sync(0xffffffffu, w, k);
            float4 v = *(const float4*)(feat + (size_t)ss * FIN + lane * 4);
            acc.x += v.x * ww; acc.y += v.y * ww;
            acc.z += v.z * ww; acc.w += v.w * ww;
        }
    }
    *(float4*)(agg + (size_t)n * FIN + lane * 4) = acc;
}

// out[n] = inorm[n] * sum_{src in N(n)} y[src] + b2      (warp per node, gather;
// y is pre-scaled by onorm in GEMM2 epilogue; finalize fused here)
__global__ void agg2_gather_kernel(const int* __restrict__ off,
                                   const int* __restrict__ csr_src,
                                   const float* __restrict__ y,
                                   const float* __restrict__ inorm,
                                   const float* __restrict__ b2,
                                   float* __restrict__ out) {
    int n = (blockIdx.x * blockDim.x + threadIdx.x) >> 5;
    if (n >= NN) return;
    int lane = threadIdx.x & 31;
    int beg = off[n], end = off[n + 1];
    float4 acc0 = make_float4(0.f, 0.f, 0.f, 0.f);
    float4 acc1 = make_float4(0.f, 0.f, 0.f, 0.f);
    for (int j = beg; j < end; j += 32) {
        int m = min(32, end - j);
        int s = (lane < m) ? __ldg(&csr_src[j + lane]) : 0;
        for (int k = 0; k < m; k++) {
            int ss = __shfl_sync(0xffffffffu, s, k);
            const float* yr = y + (size_t)ss * FOUT;
            float4 v0 = *(const float4*)(yr + lane * 4);
            float4 v1 = *(const float4*)(yr + 128 + lane * 4);
            acc0.x += v0.x; acc0.y += v0.y; acc0.z += v0.z; acc0.w += v0.w;
            acc1.x += v1.x; acc1.y += v1.y; acc1.z += v1.z; acc1.w += v1.w;
        }
    }
    float s = __ldg(&inorm[n]);
    float4 bb0 = *(const float4*)(b2 + lane * 4);
    float4 bb1 = *(const float4*)(b2 + 128 + lane * 4);
    float4 o0, o1;
    o0.x = acc0.x * s + bb0.x; o0.y = acc0.y * s + bb0.y;
    o0.z = acc0.z * s + bb0.z; o0.w = acc0.w * s + bb0.w;
    o1.x = acc1.x * s + bb1.x; o1.y = acc1.y * s + bb1.y;
    o1.z = acc1.z * s + bb1.z; o1.w = acc1.w * s + bb1.w;
    float* orow = out + (size_t)n * FOUT;
    *(float4*)(orow + lane * 4) = o0;
    *(float4*)(orow + 128 + lane * 4) = o1;
}

// ----------------------------- tf32 tensor GEMM ------------------------------
// C[M,N] = epi( (A[M,K] @ B[K,N]) * rowscale[row] (+ bias[col]) (relu) )
// BM=128, BN=64, BK=32; 256 threads = 8 warps (4 M x 2 N), warp tile 32x32.
template<bool RELU, bool HAS_BIAS>
__global__ __launch_bounds__(256)
void gemm_tf32_kernel(const float* __restrict__ A, const float* __restrict__ B,
                      float* __restrict__ C,
                      const float* __restrict__ rowscale,
                      const float* __restrict__ bias,
                      int M, int N, int K) {
    constexpr int BM = 128, BN = 64, BK = 32;
    __shared__ unsigned As[BM][BK + 4];   // stride 36: conflict-free frag loads
    __shared__ unsigned Bs[BK][BN + 4];   // stride 68: <=2-way on frag loads

    const int tid  = threadIdx.x;
    const int warp = tid >> 5;
    const int lane = tid & 31;
    const int wm = warp & 3;
    const int wn = warp >> 2;
    const int gid  = lane >> 2;
    const int tig  = lane & 3;

    const int brow0 = blockIdx.y * BM;
    const int bcol0 = blockIdx.x * BN;

    float acc[2][4][4];
#pragma unroll
    for (int mt = 0; mt < 2; mt++)
#pragma unroll
        for (int nt = 0; nt < 4; nt++)
#pragma unroll
            for (int f = 0; f < 4; f++) acc[mt][nt][f] = 0.f;

    for (int k0 = 0; k0 < K; k0 += BK) {
#pragma unroll
        for (int l = 0; l < 4; l++) {
            int idx = tid + l * 256;
            int r   = idx >> 3;
            int c4  = idx & 7;
            int grow = brow0 + r;
            float4 v = make_float4(0.f, 0.f, 0.f, 0.f);
            if (grow < M)
                v = *(const float4*)(A + (size_t)grow * K + k0 + c4 * 4);
            uint4 t;
            t.x = f2tf32(v.x); t.y = f2tf32(v.y);
            t.z = f2tf32(v.z); t.w = f2tf32(v.w);
            *(uint4*)&As[r][c4 * 4] = t;
        }
#pragma unroll
        for (int l = 0; l < 2; l++) {
            int idx = tid + l * 256;
            int kr  = idx >> 4;
            int nc4 = idx & 15;
            float4 v = *(const float4*)(B + (size_t)(k0 + kr) * N + bcol0 + nc4 * 4);
            uint4 t;
            t.x = f2tf32(v.x); t.y = f2tf32(v.y);
            t.z = f2tf32(v.z); t.w = f2tf32(v.w);
            *(uint4*)&Bs[kr][nc4 * 4] = t;
        }
        __syncthreads();

#pragma unroll
        for (int ks = 0; ks < BK; ks += 8) {
            unsigned a[2][4];
#pragma unroll
            for (int mt = 0; mt < 2; mt++) {
                int r = wm * 32 + mt * 16 + gid;
                a[mt][0] = As[r][ks + tig];
                a[mt][1] = As[r + 8][ks + tig];
                a[mt][2] = As[r][ks + 4 + tig];
                a[mt][3] = As[r + 8][ks + 4 + tig];
            }
            unsigned b[4][2];
#pragma unroll
            for (int nt = 0; nt < 4; nt++) {
                int n = wn * 32 + nt * 8 + gid;
                b[nt][0] = Bs[ks + tig][n];
                b[nt][1] = Bs[ks + 4 + tig][n];
            }
#pragma unroll
            for (int mt = 0; mt < 2; mt++)
#pragma unroll
                for (int nt = 0; nt < 4; nt++)
                    mma_tf32(acc[mt][nt][0], acc[mt][nt][1],
                             acc[mt][nt][2], acc[mt][nt][3],
                             a[mt][0], a[mt][1], a[mt][2], a[mt][3],
                             b[nt][0], b[nt][1]);
        }
        __syncthreads();
    }

#pragma unroll
    for (int mt = 0; mt < 2; mt++) {
        int r0 = brow0 + wm * 32 + mt * 16 + gid;
        int r1 = r0 + 8;
        float rs0 = (r0 < M) ? __ldg(&rowscale[r0]) : 0.f;
        float rs1 = (r1 < M) ? __ldg(&rowscale[r1]) : 0.f;
#pragma unroll
        for (int nt = 0; nt < 4; nt++) {
            int c = bcol0 + wn * 32 + nt * 8 + 2 * tig;
            float2 bb = make_float2(0.f, 0.f);
            if (HAS_BIAS) bb = *(const float2*)(bias + c);
            float2 o0, o1;
            o0.x = acc[mt][nt][0] * rs0 + bb.x;
            o0.y = acc[mt][nt][1] * rs0 + bb.y;
            o1.x = acc[mt][nt][2] * rs1 + bb.x;
            o1.y = acc[mt][nt][3] * rs1 + bb.y;
            if (RELU) {
                o0.x = fmaxf(o0.x, 0.f); o0.y = fmaxf(o0.y, 0.f);
                o1.x = fmaxf(o1.x, 0.f); o1.y = fmaxf(o1.y, 0.f);
            }
            if (r0 < M) *(float2*)(C + (size_t)r0 * N + c) = o0;
            if (r1 < M) *(float2*)(C + (size_t)r1 * N + c) = o1;
        }
    }
}

// ----------------------------- launch ---------------------------------------
extern "C" void kernel_launch(void* const* d_in, const int* in_sizes, int n_in,
                              void* d_out, int out_size) {
    const float *features = nullptr, *W1 = nullptr, *b1 = nullptr,
                *W2 = nullptr, *b2 = nullptr;
    const int* ei = nullptr;
    for (int i = 0; i < n_in; i++) {
        switch (in_sizes[i]) {
            case NN * FIN:      features = (const float*)d_in[i]; break;
            case FIN * FHID:    W1 = (const float*)d_in[i]; break;
            case FHID:          b1 = (const float*)d_in[i]; break;
            case FHID * FOUT:   W2 = (const float*)d_in[i]; break;
            case FOUT:          b2 = (const float*)d_in[i]; break;
            case 2 * NE:        ei = (const int*)d_in[i]; break;
            default: break;
        }
    }
    float* out = (float*)d_out;

    float *agg1, *x1, *y, *onorm, *inorm;
    int *dout, *din, *off, *cursor, *csr_src;
    cudaGetSymbolAddress((void**)&agg1,    g_agg1);
    cudaGetSymbolAddress((void**)&x1,      g_x1);
    cudaGetSymbolAddress((void**)&y,       g_y);
    cudaGetSymbolAddress((void**)&onorm,   g_out_norm);
    cudaGetSymbolAddress((void**)&inorm,   g_in_norm);
    cudaGetSymbolAddress((void**)&dout,    g_deg_out);
    cudaGetSymbolAddress((void**)&din,     g_deg_in);
    cudaGetSymbolAddress((void**)&off,     g_off);
    cudaGetSymbolAddress((void**)&cursor,  g_cursor);
    cudaGetSymbolAddress((void**)&csr_src, g_csr_src);

    const int T = 256;

    // Degrees (zero counters first), norms, CSR build.
    zero_int_kernel<<<(2 * NN + T - 1) / T, T>>>(dout, NN);
    zero_int_kernel<<<(NN + T - 1) / T, T>>>(din, NN);
    degree_kernel<<<(NE + T - 1) / T, T>>>(ei, dout, din);
    norm_kernel<<<(NN + T - 1) / T, T>>>(dout, din, onorm, inorm);
    scan_kernel<<<1, 1024>>>(din, off, cursor);
    scatter_kernel<<<(NE + T - 1) / T, T>>>(ei, cursor, csr_src);

    // agg1 = gather(features * onorm)   [NN, 128]
    {
        long long threads = (long long)NN * 32;
        agg1_gather_kernel<<<(unsigned)((threads + T - 1) / T), T>>>(
            off, csr_src, features, onorm, agg1);
    }

    // x1 = relu( inorm[row] * (agg1 @ W1) + b1 )   [NN, 384]
    {
        dim3 grid(FHID / 64, (NN + 127) / 128);
        gemm_tf32_kernel<true, true><<<grid, 256>>>(agg1, W1, x1, inorm, b1,
                                                    NN, FHID, FIN);
    }

    // y = onorm[row] * (x1 @ W2)   [NN, 256]
    {
        dim3 grid(FOUT / 64, (NN + 127) / 128);
        gemm_tf32_kernel<false, false><<<grid, 256>>>(x1, W2, y, onorm, nullptr,
                                                      NN, FOUT, FHID);
    }

    // out = inorm[row] * gather(y) + b2   [NN, 256]  (finalize fused)
    {
        long long threads = (long long)NN * 32;
        agg2_gather_kernel<<<(unsigned)((threads + T - 1) / T), T>>>(
            off, csr_src, y, inorm, b2, out);
    }
}

// round 4
// speedup vs baseline: 1.7373x; 1.0401x over previous
#include <cuda_runtime.h>
#include <cuda_fp16.h>
#include <cstdint>

// Problem constants (fixed shapes from reference)
#define NN   50000      // nodes
#define NE   800000     // edges
#define FIN  128
#define FHID 384
#define FOUT 256

// ----------------------------- scratch (device globals; no allocs allowed) ---
__device__ float  g_agg1[NN * FIN];            // 25.6 MB
__device__ float  g_x1[(size_t)NN * FHID];     // 76.8 MB
__device__ __half g_y_h[(size_t)NN * FOUT];    // 25.6 MB (fp16 y)
__device__ __half g_feat_h[NN * FIN];          // 12.8 MB (fp16 features)
__device__ int    g_deg_out[NN];
__device__ int    g_deg_in[NN];
__device__ float  g_out_norm[NN];
__device__ float  g_in_norm[NN];
__device__ int    g_off[NN + 1];
__device__ int    g_cursor[NN];
__device__ int    g_csr_src[NE];

// ----------------------------- helpers --------------------------------------
__device__ __forceinline__ unsigned f2tf32(float x) {
    unsigned r;
    asm("cvt.rna.tf32.f32 %0, %1;" : "=r"(r) : "f"(x));
    return r;
}

__device__ __forceinline__ void mma_tf32(float& c0, float& c1, float& c2, float& c3,
                                         unsigned a0, unsigned a1, unsigned a2, unsigned a3,
                                         unsigned b0, unsigned b1) {
    asm volatile("mma.sync.aligned.m16n8k8.row.col.f32.tf32.tf32.f32 "
                 "{%0,%1,%2,%3}, {%4,%5,%6,%7}, {%8,%9}, {%0,%1,%2,%3};"
                 : "+f"(c0), "+f"(c1), "+f"(c2), "+f"(c3)
                 : "r"(a0), "r"(a1), "r"(a2), "r"(a3), "r"(b0), "r"(b1));
}

__device__ __forceinline__ unsigned h2bits(__half2 h) {
    return *reinterpret_cast<unsigned*>(&h);
}
__device__ __forceinline__ __half2 bits2h(unsigned u) {
    return *reinterpret_cast<__half2*>(&u);
}

// ----------------------------- small kernels --------------------------------
__global__ void zero_int_kernel(int* __restrict__ p, int n) {
    int i = blockIdx.x * blockDim.x + threadIdx.x;
    if (i < n) p[i] = 0;
}

__global__ void f2h_kernel(const float4* __restrict__ in, uint2* __restrict__ out, int n4) {
    int i = blockIdx.x * blockDim.x + threadIdx.x;
    if (i < n4) {
        float4 v = in[i];
        __half2 h0 = __floats2half2_rn(v.x, v.y);
        __half2 h1 = __floats2half2_rn(v.z, v.w);
        out[i] = make_uint2(h2bits(h0), h2bits(h1));
    }
}

__global__ void degree_kernel(const int* __restrict__ ei,
                              int* __restrict__ dout, int* __restrict__ din) {
    int e = blockIdx.x * blockDim.x + threadIdx.x;
    if (e < NE) {
        atomicAdd(&dout[ei[e]], 1);
        atomicAdd(&din[ei[NE + e]], 1);
    }
}

__global__ void norm_kernel(const int* __restrict__ dout, const int* __restrict__ din,
                            float* __restrict__ onorm, float* __restrict__ inorm) {
    int n = blockIdx.x * blockDim.x + threadIdx.x;
    if (n < NN) {
        onorm[n] = rsqrtf((float)max(dout[n], 1));
        inorm[n] = rsqrtf((float)max(din[n], 1));
    }
}

// Single-block exclusive scan over deg_in -> off, cursor (50k ints).
__global__ void scan_kernel(const int* __restrict__ deg,
                            int* __restrict__ off, int* __restrict__ cursor) {
    constexpr int T = 1024;
    constexpr int CHUNK = (NN + T - 1) / T;   // 49
    __shared__ int ssum[T];
    int t = threadIdx.x;
    int base = t * CHUNK;
    int s = 0;
#pragma unroll 4
    for (int i = 0; i < CHUNK; i++) {
        int idx = base + i;
        if (idx < NN) s += deg[idx];
    }
    ssum[t] = s;
    __syncthreads();
    for (int d = 1; d < T; d <<= 1) {
        int v = (t >= d) ? ssum[t - d] : 0;
        __syncthreads();
        if (t >= d) ssum[t] += v;
        __syncthreads();
    }
    int run = (t > 0) ? ssum[t - 1] : 0;
    for (int i = 0; i < CHUNK; i++) {
        int idx = base + i;
        if (idx < NN) {
            off[idx] = run;
            cursor[idx] = run;
            run += deg[idx];
        }
    }
    if (t == T - 1) off[NN] = NE;
}

__global__ void scatter_kernel(const int* __restrict__ ei,
                               int* __restrict__ cursor,
                               int* __restrict__ csr_src) {
    int e = blockIdx.x * blockDim.x + threadIdx.x;
    if (e < NE) {
        int src = ei[e];
        int dst = ei[NE + e];
        int pos = atomicAdd(&cursor[dst], 1);
        csr_src[pos] = src;
    }
}

// agg1[n] = sum_{src in N(n)} feat_h[src] * onorm[src]   (warp per node; fp16 reads)
__global__ void agg1_gather_kernel(const int* __restrict__ off,
                                   const int* __restrict__ csr_src,
                                   const __half* __restrict__ feat,
                                   const float* __restrict__ onorm,
                                   float* __restrict__ agg) {
    int n = (blockIdx.x * blockDim.x + threadIdx.x) >> 5;
    if (n >= NN) return;
    int lane = threadIdx.x & 31;
    int beg = off[n], end = off[n + 1];
    float4 acc = make_float4(0.f, 0.f, 0.f, 0.f);
    for (int j = beg; j < end; j += 32) {
        int m = min(32, end - j);
        int s  = (lane < m) ? __ldg(&csr_src[j + lane]) : 0;
        float w = (lane < m) ? __ldg(&onorm[s]) : 0.f;
        for (int k = 0; k < m; k++) {
            int   ss = __shfl_sync(0xffffffffu, s, k);
            float ww = __shfl_sync(0xffffffffu, w, k);
            uint2 u = *(const uint2*)(feat + (size_t)ss * FIN + lane * 4);
            float2 f0 = __half22float2(bits2h(u.x));
            float2 f1 = __half22float2(bits2h(u.y));
            acc.x += f0.x * ww; acc.y += f0.y * ww;
            acc.z += f1.x * ww; acc.w += f1.y * ww;
        }
    }
    *(float4*)(agg + (size_t)n * FIN + lane * 4) = acc;
}

// out[n] = inorm[n] * sum_{src in N(n)} y_h[src] + b2   (warp per node; fp16 reads)
__global__ void agg2_gather_kernel(const int* __restrict__ off,
                                   const int* __restrict__ csr_src,
                                   const __half* __restrict__ y,
                                   const float* __restrict__ inorm,
                                   const float* __restrict__ b2,
                                   float* __restrict__ out) {
    int n = (blockIdx.x * blockDim.x + threadIdx.x) >> 5;
    if (n >= NN) return;
    int lane = threadIdx.x & 31;
    int beg = off[n], end = off[n + 1];
    float acc[8] = {0.f, 0.f, 0.f, 0.f, 0.f, 0.f, 0.f, 0.f};
    for (int j = beg; j < end; j += 32) {
        int m = min(32, end - j);
        int s = (lane < m) ? __ldg(&csr_src[j + lane]) : 0;
        for (int k = 0; k < m; k++) {
            int ss = __shfl_sync(0xffffffffu, s, k);
            uint4 u = *(const uint4*)(y + (size_t)ss * FOUT + lane * 8);
            float2 f0 = __half22float2(bits2h(u.x));
            float2 f1 = __half22float2(bits2h(u.y));
            float2 f2 = __half22float2(bits2h(u.z));
            float2 f3 = __half22float2(bits2h(u.w));
            acc[0] += f0.x; acc[1] += f0.y; acc[2] += f1.x; acc[3] += f1.y;
            acc[4] += f2.x; acc[5] += f2.y; acc[6] += f3.x; acc[7] += f3.y;
        }
    }
    float s = __ldg(&inorm[n]);
    float4 bb0 = *(const float4*)(b2 + lane * 8);
    float4 bb1 = *(const float4*)(b2 + lane * 8 + 4);
    float4 o0, o1;
    o0.x = acc[0] * s + bb0.x; o0.y = acc[1] * s + bb0.y;
    o0.z = acc[2] * s + bb0.z; o0.w = acc[3] * s + bb0.w;
    o1.x = acc[4] * s + bb1.x; o1.y = acc[5] * s + bb1.y;
    o1.z = acc[6] * s + bb1.z; o1.w = acc[7] * s + bb1.w;
    float* orow = out + (size_t)n * FOUT + lane * 8;
    *(float4*)orow = o0;
    *(float4*)(orow + 4) = o1;
}

// ----------------------------- tf32 tensor GEMM ------------------------------
// C = epi( (A[M,K] @ B[K,N]) * rowscale[row] (+ bias) (relu) ), C fp32 or fp16.
// BM=128, BN=64, BK=32; 256 threads = 8 warps (4 M x 2 N), warp tile 32x32.
// Double-buffered smem + register prefetch: one barrier per K-tile.
template<bool RELU, bool HAS_BIAS, bool OUT_HALF>
__global__ __launch_bounds__(256)
void gemm_tf32_kernel(const float* __restrict__ A, const float* __restrict__ B,
                      void* __restrict__ Cv,
                      const float* __restrict__ rowscale,
                      const float* __restrict__ bias,
                      int M, int N, int K) {
    constexpr int BM = 128, BN = 64, BK = 32;
    __shared__ unsigned As[2][BM][BK + 4];   // conflict-free scalar frag reads
    __shared__ unsigned Bs[2][BK][BN + 4];

    const int tid  = threadIdx.x;
    const int warp = tid >> 5;
    const int lane = tid & 31;
    const int wm = warp & 3;
    const int wn = warp >> 2;
    const int gid  = lane >> 2;
    const int tig  = lane & 3;

    const int brow0 = blockIdx.y * BM;
    const int bcol0 = blockIdx.x * BN;

    // per-thread staging coordinates
    const int a_r  = tid >> 1;                 // pair-based: 2 float4 per row? no:
    // A: 128x32 = 1024 float4, 4/thread: idx = tid + l*256 -> r = idx>>3, c4 = idx&7
    // B: 32x64  = 512 float4,  2/thread: idx = tid + l*256 -> kr = idx>>4, nc4 = idx&15

    float acc[2][4][4];
#pragma unroll
    for (int mt = 0; mt < 2; mt++)
#pragma unroll
        for (int nt = 0; nt < 4; nt++)
#pragma unroll
            for (int f = 0; f < 4; f++) acc[mt][nt][f] = 0.f;

    float4 ra[4];
    float4 rb[2];

    auto load_tile = [&](int k0) {
#pragma unroll
        for (int l = 0; l < 4; l++) {
            int idx = tid + l * 256;
            int r   = idx >> 3;
            int c4  = idx & 7;
            int grow = brow0 + r;
            ra[l] = make_float4(0.f, 0.f, 0.f, 0.f);
            if (grow < M)
                ra[l] = *(const float4*)(A + (size_t)grow * K + k0 + c4 * 4);
        }
#pragma unroll
        for (int l = 0; l < 2; l++) {
            int idx = tid + l * 256;
            int kr  = idx >> 4;
            int nc4 = idx & 15;
            rb[l] = *(const float4*)(B + (size_t)(k0 + kr) * N + bcol0 + nc4 * 4);
        }
    };

    load_tile(0);
    int buf = 0;

    for (int k0 = 0; k0 < K; k0 += BK) {
        // store staged regs (with tf32 conversion)
#pragma unroll
        for (int l = 0; l < 4; l++) {
            int idx = tid + l * 256;
            int r   = idx >> 3;
            int c4  = idx & 7;
            As[buf][r][c4 * 4 + 0] = f2tf32(ra[l].x);
            As[buf][r][c4 * 4 + 1] = f2tf32(ra[l].y);
            As[buf][r][c4 * 4 + 2] = f2tf32(ra[l].z);
            As[buf][r][c4 * 4 + 3] = f2tf32(ra[l].w);
        }
#pragma unroll
        for (int l = 0; l < 2; l++) {
            int idx = tid + l * 256;
            int kr  = idx >> 4;
            int nc4 = idx & 15;
            Bs[buf][kr][nc4 * 4 + 0] = f2tf32(rb[l].x);
            Bs[buf][kr][nc4 * 4 + 1] = f2tf32(rb[l].y);
            Bs[buf][kr][nc4 * 4 + 2] = f2tf32(rb[l].z);
            Bs[buf][kr][nc4 * 4 + 3] = f2tf32(rb[l].w);
        }
        __syncthreads();

        if (k0 + BK < K) load_tile(k0 + BK);   // prefetch next tile (overlaps mma)

#pragma unroll
        for (int ks = 0; ks < BK; ks += 8) {
            unsigned a[2][4];
#pragma unroll
            for (int mt = 0; mt < 2; mt++) {
                int r = wm * 32 + mt * 16 + gid;
                a[mt][0] = As[buf][r][ks + tig];
                a[mt][1] = As[buf][r + 8][ks + tig];
                a[mt][2] = As[buf][r][ks + 4 + tig];
                a[mt][3] = As[buf][r + 8][ks + 4 + tig];
            }
            unsigned b[4][2];
#pragma unroll
            for (int nt = 0; nt < 4; nt++) {
                int n = wn * 32 + nt * 8 + gid;
                b[nt][0] = Bs[buf][ks + tig][n];
                b[nt][1] = Bs[buf][ks + 4 + tig][n];
            }
#pragma unroll
            for (int mt = 0; mt < 2; mt++)
#pragma unroll
                for (int nt = 0; nt < 4; nt++)
                    mma_tf32(acc[mt][nt][0], acc[mt][nt][1],
                             acc[mt][nt][2], acc[mt][nt][3],
                             a[mt][0], a[mt][1], a[mt][2], a[mt][3],
                             b[nt][0], b[nt][1]);
        }
        buf ^= 1;
    }

    // ---- Epilogue
#pragma unroll
    for (int mt = 0; mt < 2; mt++) {
        int r0 = brow0 + wm * 32 + mt * 16 + gid;
        int r1 = r0 + 8;
        float rs0 = (r0 < M) ? __ldg(&rowscale[r0]) : 0.f;
        float rs1 = (r1 < M) ? __ldg(&rowscale[r1]) : 0.f;
#pragma unroll
        for (int nt = 0; nt < 4; nt++) {
            int c = bcol0 + wn * 32 + nt * 8 + 2 * tig;
            float2 bb = make_float2(0.f, 0.f);
            if (HAS_BIAS) bb = *(const float2*)(bias + c);
            float2 o0, o1;
            o0.x = acc[mt][nt][0] * rs0 + bb.x;
            o0.y = acc[mt][nt][1] * rs0 + bb.y;
            o1.x = acc[mt][nt][2] * rs1 + bb.x;
            o1.y = acc[mt][nt][3] * rs1 + bb.y;
            if (RELU) {
                o0.x = fmaxf(o0.x, 0.f); o0.y = fmaxf(o0.y, 0.f);
                o1.x = fmaxf(o1.x, 0.f); o1.y = fmaxf(o1.y, 0.f);
            }
            if (OUT_HALF) {
                __half* C = (__half*)Cv;
                if (r0 < M) *(__half2*)(C + (size_t)r0 * N + c) = __floats2half2_rn(o0.x, o0.y);
                if (r1 < M) *(__half2*)(C + (size_t)r1 * N + c) = __floats2half2_rn(o1.x, o1.y);
            } else {
                float* C = (float*)Cv;
                if (r0 < M) *(float2*)(C + (size_t)r0 * N + c) = o0;
                if (r1 < M) *(float2*)(C + (size_t)r1 * N + c) = o1;
            }
        }
    }
}

// ----------------------------- launch ---------------------------------------
extern "C" void kernel_launch(void* const* d_in, const int* in_sizes, int n_in,
                              void* d_out, int out_size) {
    const float *features = nullptr, *W1 = nullptr, *b1 = nullptr,
                *W2 = nullptr, *b2 = nullptr;
    const int* ei = nullptr;
    for (int i = 0; i < n_in; i++) {
        switch (in_sizes[i]) {
            case NN * FIN:      features = (const float*)d_in[i]; break;
            case FIN * FHID:    W1 = (const float*)d_in[i]; break;
            case FHID:          b1 = (const float*)d_in[i]; break;
            case FHID * FOUT:   W2 = (const float*)d_in[i]; break;
            case FOUT:          b2 = (const float*)d_in[i]; break;
            case 2 * NE:        ei = (const int*)d_in[i]; break;
            default: break;
        }
    }
    float* out = (float*)d_out;

    float *agg1, *x1, *onorm, *inorm;
    __half *y_h, *feat_h;
    int *dout, *din, *off, *cursor, *csr_src;
    cudaGetSymbolAddress((void**)&agg1,    g_agg1);
    cudaGetSymbolAddress((void**)&x1,      g_x1);
    cudaGetSymbolAddress((void**)&y_h,     g_y_h);
    cudaGetSymbolAddress((void**)&feat_h,  g_feat_h);
    cudaGetSymbolAddress((void**)&onorm,   g_out_norm);
    cudaGetSymbolAddress((void**)&inorm,   g_in_norm);
    cudaGetSymbolAddress((void**)&dout,    g_deg_out);
    cudaGetSymbolAddress((void**)&din,     g_deg_in);
    cudaGetSymbolAddress((void**)&off,     g_off);
    cudaGetSymbolAddress((void**)&cursor,  g_cursor);
    cudaGetSymbolAddress((void**)&csr_src, g_csr_src);

    const int T = 256;

    // fp16 copy of features (independent of CSR chain)
    {
        int n4 = NN * FIN / 4;
        f2h_kernel<<<(n4 + T - 1) / T, T>>>((const float4*)features, (uint2*)feat_h, n4);
    }

    // Degrees, norms, CSR build.
    zero_int_kernel<<<(NN + T - 1) / T, T>>>(dout, NN);
    zero_int_kernel<<<(NN + T - 1) / T, T>>>(din, NN);
    degree_kernel<<<(NE + T - 1) / T, T>>>(ei, dout, din);
    norm_kernel<<<(NN + T - 1) / T, T>>>(dout, din, onorm, inorm);
    scan_kernel<<<1, 1024>>>(din, off, cursor);
    scatter_kernel<<<(NE + T - 1) / T, T>>>(ei, cursor, csr_src);

    // agg1 = gather(feat_h * onorm)   [NN, 128]
    {
        long long threads = (long long)NN * 32;
        agg1_gather_kernel<<<(unsigned)((threads + T - 1) / T), T>>>(
            off, csr_src, feat_h, onorm, agg1);
    }

    // x1 = relu( inorm[row] * (agg1 @ W1) + b1 )   [NN, 384] fp32
    {
        dim3 grid(FHID / 64, (NN + 127) / 128);
        gemm_tf32_kernel<true, true, false><<<grid, 256>>>(agg1, W1, x1, inorm, b1,
                                                           NN, FHID, FIN);
    }

    // y_h = fp16( onorm[row] * (x1 @ W2) )   [NN, 256]
    {
        dim3 grid(FOUT / 64, (NN + 127) / 128);
        gemm_tf32_kernel<false, false, true><<<grid, 256>>>(x1, W2, y_h, onorm, nullptr,
                                                            NN, FOUT, FHID);
    }

    // out = inorm[row] * gather(y_h) + b2   [NN, 256]
    {
        long long threads = (long long)NN * 32;
        agg2_gather_kernel<<<(unsigned)((threads + T - 1) / T), T>>>(
            off, csr_src, y_h, inorm, b2, out);
    }
}